// round 1
// baseline (speedup 1.0000x reference)
#include <cuda_runtime.h>

namespace {

constexpr int NPG = 64;   // nodes per graph
constexpr int NB  = 64;   // graphs (blocks)
constexpr int NT  = 512;  // threads per block (16 warps)

struct Smem {
  float A [64][64];   // adjacency block
  float F [64][64];   // feat (initial, constant through loop)
  float H [64][64];   // all_feat_head
  float T [64][64];   // all_feat_tail
  float U1[64][64];   // scratch: xcat staging, then up1
  float U2[64][64];   // up2
  float W1[64][64];
  float W2[64][64];
  float TR[64][64];
  float cor1[64], cor2[64], deg[64];
  float fh[3][64], ft[3][64];
  float g1[64], be1[64], g2[64], be2[64], bb1[64], bb2[64];
};

__device__ __forceinline__ float wsum(float v) {
  #pragma unroll
  for (int o = 16; o > 0; o >>= 1) v += __shfl_xor_sync(0xFFFFFFFFu, v, o);
  return v;
}

__global__ __launch_bounds__(NT, 1)
void lagat_kernel(const float* __restrict__ adj,
                  const float* __restrict__ feat_node,
                  const int*   __restrict__ idx,
                  const int*   __restrict__ head_ids,
                  const int*   __restrict__ tail_ids,
                  const float* __restrict__ transform,
                  const float* __restrict__ embed,
                  const float* __restrict__ w1, const float* __restrict__ b1,
                  const float* __restrict__ w2, const float* __restrict__ b2,
                  const float* __restrict__ gamma1, const float* __restrict__ beta1,
                  const float* __restrict__ gamma2, const float* __restrict__ beta2,
                  float* __restrict__ out)
{
  extern __shared__ float smem_raw[];
  Smem& s = *reinterpret_cast<Smem*>(smem_raw);
  const int g   = blockIdx.x;
  const int tid = threadIdx.x;
  const int w   = tid >> 5;
  const int l   = tid & 31;
  const int base = g * NPG;

  // ---------------- loads: adj block, weights, xcat (staged in U1) ----------
  #pragma unroll
  for (int e = tid; e < 4096; e += NT) {
    const int i = e >> 6, j = e & 63;
    s.A[i][j]  = adj[(size_t)(base + i) * 4096 + base + j];
    s.TR[i][j] = transform[e];
    s.W1[i][j] = w1[e];
    s.W2[i][j] = w2[e];
    float x;
    if (j < 32) x = feat_node[(base + i) * 32 + j];
    else        x = embed[(size_t)idx[base + i] * 32 + (j - 32)];
    s.U1[i][j] = x;
  }
  if (tid < 64) {
    s.g1[tid]  = gamma1[tid]; s.be1[tid] = beta1[tid];
    s.g2[tid]  = gamma2[tid]; s.be2[tid] = beta2[tid];
    s.bb1[tid] = b1[tid];     s.bb2[tid] = b2[tid];
  }
  const int hl = head_ids[g] - base;   // local head index
  const int tl = tail_ids[g] - base;   // local tail index
  if (tid < 64) {
    s.fh[0][tid] = (tid == hl) ? 1.f : 0.f;
    s.ft[0][tid] = (tid == tl) ? 1.f : 0.f;
  }
  __syncthreads();

  // ---------------- feat = xcat @ TR ; init H,T ; deg ; out layer 0 ---------
  #pragma unroll
  for (int rr = 0; rr < 4; ++rr) {
    const int r = w * 4 + rr;
    float a0 = 0.f, a1 = 0.f;
    #pragma unroll
    for (int k = 0; k < 64; ++k) {
      const float x = s.U1[r][k];
      a0 = fmaf(x, s.TR[k][l],      a0);
      a1 = fmaf(x, s.TR[k][l + 32], a1);
    }
    s.F[r][l] = a0; s.F[r][l+32] = a1;
    s.H[r][l] = a0; s.H[r][l+32] = a1;
    s.T[r][l] = a0; s.T[r][l+32] = a1;
    const float d = wsum(s.A[r][l] + s.A[r][l+32]);
    if (l == 0) s.deg[r] = d;
    const size_t ob = (size_t)(base + r) * 256;
    out[ob + l] = a0; out[ob + l + 32] = a1;
  }
  __syncthreads();

  // ---------------- BFS frontiers: fh[k] = nodes within k hops of head ------
  #pragma unroll
  for (int k = 1; k < 3; ++k) {
    #pragma unroll
    for (int rr = 0; rr < 4; ++rr) {
      const int r = w * 4 + rr;
      float vh = s.A[r][l] * s.fh[k-1][l] + s.A[r][l+32] * s.fh[k-1][l+32];
      float vt = s.A[r][l] * s.ft[k-1][l] + s.A[r][l+32] * s.ft[k-1][l+32];
      vh = wsum(vh); vt = wsum(vt);
      if (l == 0) {
        s.fh[k][r] = (vh > 0.f || s.fh[k-1][r] > 0.f) ? 1.f : 0.f;
        s.ft[k][r] = (vt > 0.f || s.ft[k-1][r] > 0.f) ? 1.f : 0.f;
      }
    }
    __syncthreads();
  }

  // ---------------- main loop: hop = 2, 1, 0 --------------------------------
  for (int it = 0; it < 3; ++it) {
    const int hop = 2 - it;

    // correlations: cor1[r] = |<F[tl], H[r]>|, cor2[r] = |<F[hl], T[r]>|
    #pragma unroll
    for (int rr = 0; rr < 4; ++rr) {
      const int r = w * 4 + rr;
      float c1 = s.F[tl][l] * s.H[r][l] + s.F[tl][l+32] * s.H[r][l+32];
      float c2 = s.F[hl][l] * s.T[r][l] + s.F[hl][l+32] * s.T[r][l+32];
      c1 = wsum(c1); c2 = wsum(c2);
      if (l == 0) { s.cor1[r] = fabsf(c1); s.cor2[r] = fabsf(c2); }
    }
    __syncthreads();

    // masked aggregation + leaky_relu + mean-div + LayerNorm -> U1 / U2
    #pragma unroll
    for (int rr = 0; rr < 4; ++rr) {
      const int r = w * 4 + rr;
      if (s.fh[hop][r] > 0.f) {
        float a0 = 0.f, a1 = 0.f;
        for (int j = 0; j < 64; ++j) {
          const float c = s.A[r][j];            // uniform across warp
          if (c > 0.f) {
            const float cc = c * s.cor1[j];
            a0 = fmaf(cc, s.H[j][l],      a0);
            a1 = fmaf(cc, s.H[j][l + 32], a1);
          }
        }
        a0 = (a0 >= 0.f) ? a0 : 0.01f * a0;
        a1 = (a1 >= 0.f) ? a1 : 0.01f * a1;
        const float inv = 1.f / (s.deg[r] + 1e-8f);
        a0 *= inv; a1 *= inv;
        const float mu  = wsum(a0 + a1) * (1.f / 64.f);
        const float d0  = a0 - mu, d1 = a1 - mu;
        const float var = wsum(d0 * d0 + d1 * d1) * (1.f / 64.f);
        const float rs  = rsqrtf(var + 1e-5f);
        s.U1[r][l]      = fmaf(s.g1[l]      * rs, d0, s.be1[l]);
        s.U1[r][l + 32] = fmaf(s.g1[l + 32] * rs, d1, s.be1[l + 32]);
      }
      if (s.ft[hop][r] > 0.f) {
        float a0 = 0.f, a1 = 0.f;
        for (int j = 0; j < 64; ++j) {
          const float c = s.A[r][j];
          if (c > 0.f) {
            const float cc = c * s.cor2[j];
            a0 = fmaf(cc, s.T[j][l],      a0);
            a1 = fmaf(cc, s.T[j][l + 32], a1);
          }
        }
        a0 = (a0 >= 0.f) ? a0 : 0.01f * a0;
        a1 = (a1 >= 0.f) ? a1 : 0.01f * a1;
        const float inv = 1.f / (s.deg[r] + 1e-8f);
        a0 *= inv; a1 *= inv;
        const float mu  = wsum(a0 + a1) * (1.f / 64.f);
        const float d0  = a0 - mu, d1 = a1 - mu;
        const float var = wsum(d0 * d0 + d1 * d1) * (1.f / 64.f);
        const float rs  = rsqrtf(var + 1e-5f);
        s.U2[r][l]      = fmaf(s.g2[l]      * rs, d0, s.be2[l]);
        s.U2[r][l + 32] = fmaf(s.g2[l + 32] * rs, d1, s.be2[l + 32]);
      }
    }
    __syncthreads();

    // aggregator GEMMs: H[r] = relu((F[r]+U1[r]) @ W1 + b1) on frontier rows
    #pragma unroll
    for (int rr = 0; rr < 4; ++rr) {
      const int r = w * 4 + rr;
      if (s.fh[hop][r] > 0.f) {
        float a0 = s.bb1[l], a1 = s.bb1[l + 32];
        #pragma unroll
        for (int k = 0; k < 64; ++k) {
          const float x = s.F[r][k] + s.U1[r][k];
          a0 = fmaf(x, s.W1[k][l],      a0);
          a1 = fmaf(x, s.W1[k][l + 32], a1);
        }
        s.H[r][l]      = fmaxf(a0, 0.f);
        s.H[r][l + 32] = fmaxf(a1, 0.f);
      }
      if (s.ft[hop][r] > 0.f) {
        float a0 = s.bb2[l], a1 = s.bb2[l + 32];
        #pragma unroll
        for (int k = 0; k < 64; ++k) {
          const float x = s.F[r][k] + s.U2[r][k];
          a0 = fmaf(x, s.W2[k][l],      a0);
          a1 = fmaf(x, s.W2[k][l + 32], a1);
        }
        s.T[r][l]      = fmaxf(a0, 0.f);
        s.T[r][l + 32] = fmaxf(a1, 0.f);
      }
    }
    __syncthreads();

    // emit layer it+1 = H + T
    #pragma unroll
    for (int rr = 0; rr < 4; ++rr) {
      const int r = w * 4 + rr;
      const size_t ob = (size_t)(base + r) * 256 + (size_t)(it + 1) * 64;
      out[ob + l]      = s.H[r][l]      + s.T[r][l];
      out[ob + l + 32] = s.H[r][l + 32] + s.T[r][l + 32];
    }
    __syncthreads();
  }
}

} // namespace

extern "C" void kernel_launch(void* const* d_in, const int* in_sizes, int n_in,
                              void* d_out, int out_size) {
  const float* adj       = (const float*)d_in[0];
  const float* feat_node = (const float*)d_in[1];
  const int*   idx       = (const int*)  d_in[2];
  const int*   head_ids  = (const int*)  d_in[3];
  const int*   tail_ids  = (const int*)  d_in[4];
  // d_in[5] = graph_indices (structure implicit in block layout; unused)
  const float* transform = (const float*)d_in[6];
  const float* embed     = (const float*)d_in[7];
  const float* w1        = (const float*)d_in[8];
  const float* b1        = (const float*)d_in[9];
  const float* w2        = (const float*)d_in[10];
  const float* b2        = (const float*)d_in[11];
  const float* gamma1    = (const float*)d_in[12];
  const float* beta1     = (const float*)d_in[13];
  const float* gamma2    = (const float*)d_in[14];
  const float* beta2     = (const float*)d_in[15];
  float* out = (float*)d_out;

  const int smem = (int)sizeof(Smem);
  cudaFuncSetAttribute(lagat_kernel, cudaFuncAttributeMaxDynamicSharedMemorySize, smem);
  lagat_kernel<<<NB, NT, smem>>>(adj, feat_node, idx, head_ids, tail_ids,
                                 transform, embed, w1, b1, w2, b2,
                                 gamma1, beta1, gamma2, beta2, out);
}

// round 2
// speedup vs baseline: 1.5035x; 1.5035x over previous
#include <cuda_runtime.h>

namespace {

constexpr int NB = 64;   // graphs (blocks)
constexpr int NT = 512;  // threads per block (16 warps)

struct Smem {
  float A [64][64];
  float F [64][64];
  float H [64][64];
  float T [64][64];
  float U1[64][64];   // xcat staging, then F + LN-out (head side)
  float U2[64][64];   // F + LN-out (tail side)
  float W1[64][64];
  float W2[64][64];
  float TR[64][64];
  float WE1[64][64];  // cor1[j] * H[j][:]
  float WE2[64][64];  // cor2[j] * T[j][:]
  float degf[64];
  float g1[64], be1[64], g2[64], be2[64], bb1[64], bb2[64];
  float fh[3][64], ft[3][64];
  int   ncnt[3];
  unsigned char nbr[64][64];
  unsigned char tasks[3][128];   // (side<<6)|row, head tasks then tail tasks
};

__device__ __forceinline__ float rsum16(float v, unsigned m) {
  v += __shfl_xor_sync(m, v, 8);
  v += __shfl_xor_sync(m, v, 4);
  v += __shfl_xor_sync(m, v, 2);
  v += __shfl_xor_sync(m, v, 1);
  return v;
}

__device__ __forceinline__ void fma4(float4& a, float s, const float4& b) {
  a.x = fmaf(s, b.x, a.x); a.y = fmaf(s, b.y, a.y);
  a.z = fmaf(s, b.z, a.z); a.w = fmaf(s, b.w, a.w);
}

__global__ __launch_bounds__(NT, 1)
void lagat_kernel(const float* __restrict__ adj,
                  const float* __restrict__ feat_node,
                  const int*   __restrict__ idx,
                  const int*   __restrict__ head_ids,
                  const int*   __restrict__ tail_ids,
                  const float* __restrict__ transform,
                  const float* __restrict__ embed,
                  const float* __restrict__ w1, const float* __restrict__ b1,
                  const float* __restrict__ w2, const float* __restrict__ b2,
                  const float* __restrict__ gamma1, const float* __restrict__ beta1,
                  const float* __restrict__ gamma2, const float* __restrict__ beta2,
                  float* __restrict__ out)
{
  extern __shared__ float smem_raw[];
  Smem& s = *reinterpret_cast<Smem*>(smem_raw);
  const int g    = blockIdx.x;
  const int tid  = threadIdx.x;
  const int w    = tid >> 5;
  const int l    = tid & 31;
  const int li   = l & 15;
  const int h16  = l >> 4;
  const unsigned hm = (l < 16) ? 0x0000FFFFu : 0xFFFF0000u;
  const int base = g * 64;

  float4* A4   = reinterpret_cast<float4*>(&s.A [0][0]);
  float4* F4   = reinterpret_cast<float4*>(&s.F [0][0]);
  float4* H4   = reinterpret_cast<float4*>(&s.H [0][0]);
  float4* T4   = reinterpret_cast<float4*>(&s.T [0][0]);
  float4* U14  = reinterpret_cast<float4*>(&s.U1[0][0]);
  float4* U24  = reinterpret_cast<float4*>(&s.U2[0][0]);
  float4* W14  = reinterpret_cast<float4*>(&s.W1[0][0]);
  float4* W24  = reinterpret_cast<float4*>(&s.W2[0][0]);
  float4* TR4  = reinterpret_cast<float4*>(&s.TR[0][0]);
  float4* WE14 = reinterpret_cast<float4*>(&s.WE1[0][0]);
  float4* WE24 = reinterpret_cast<float4*>(&s.WE2[0][0]);
  const float4* g1_4  = reinterpret_cast<const float4*>(s.g1);
  const float4* be1_4 = reinterpret_cast<const float4*>(s.be1);
  const float4* g2_4  = reinterpret_cast<const float4*>(s.g2);
  const float4* be2_4 = reinterpret_cast<const float4*>(s.be2);
  const float4* bb1_4 = reinterpret_cast<const float4*>(s.bb1);
  const float4* bb2_4 = reinterpret_cast<const float4*>(s.bb2);

  const int hl = head_ids[g] - base;
  const int tl = tail_ids[g] - base;

  // ---------------- P0: global loads (all float4) ---------------------------
  #pragma unroll
  for (int e = tid; e < 1024; e += NT) {
    const int i = e >> 4, j = e & 15;
    A4[e] = *reinterpret_cast<const float4*>(adj + (size_t)(base + i) * 4096 + base + j * 4);
  }
  #pragma unroll
  for (int e = tid; e < 1024; e += NT) {
    TR4[e] = reinterpret_cast<const float4*>(transform)[e];
    W14[e] = reinterpret_cast<const float4*>(w1)[e];
    W24[e] = reinterpret_cast<const float4*>(w2)[e];
  }
  {
    // xcat -> U1: [feat_node(32) | embed[idx](32)], 512 threads = 64 rows x 8 f4
    const int i = tid >> 3, j = tid & 7;
    U14[i * 16 + j] = *reinterpret_cast<const float4*>(feat_node + (base + i) * 32 + j * 4);
    const int id = idx[base + i];
    U14[i * 16 + 8 + j] = *reinterpret_cast<const float4*>(embed + (size_t)id * 32 + j * 4);
  }
  if (tid < 64) {
    s.g1[tid] = gamma1[tid]; s.be1[tid] = beta1[tid];
    s.g2[tid] = gamma2[tid]; s.be2[tid] = beta2[tid];
    s.bb1[tid] = b1[tid];    s.bb2[tid] = b2[tid];
  }
  __syncthreads();

  // ---------------- P1: feat = xcat @ TR ; init H,T ; out layer 0 -----------
  #pragma unroll
  for (int p = 0; p < 2; ++p) {
    const int r = w * 4 + p * 2 + h16;
    float4 acc = make_float4(0.f, 0.f, 0.f, 0.f);
    #pragma unroll
    for (int kb = 0; kb < 16; ++kb) {
      const float4 xv = U14[r * 16 + kb];
      fma4(acc, xv.x, TR4[(4 * kb + 0) * 16 + li]);
      fma4(acc, xv.y, TR4[(4 * kb + 1) * 16 + li]);
      fma4(acc, xv.z, TR4[(4 * kb + 2) * 16 + li]);
      fma4(acc, xv.w, TR4[(4 * kb + 3) * 16 + li]);
    }
    F4[r * 16 + li] = acc;
    H4[r * 16 + li] = acc;
    T4[r * 16 + li] = acc;
    *reinterpret_cast<float4*>(out + (size_t)(base + r) * 256 + li * 4) = acc;
  }
  __syncthreads();

  // ---------------- P2a: neighbor lists + degrees + frontiers (tid<64) ------
  if (tid < 64) {
    const int t = tid;
    int c = 0;
    for (int j = 0; j < 64; ++j) {
      if (s.A[j][t] != 0.f) { s.nbr[t][c] = (unsigned char)j; ++c; }  // symmetric: col t == row t
    }
    s.degf[t] = (float)c;
    bool f1 = (t == hl) || (s.A[hl][t] != 0.f);
    bool e1 = (t == tl) || (s.A[tl][t] != 0.f);
    bool f2 = f1, e2 = e1;
    for (int i = 0; i < c; ++i) {
      const int j = s.nbr[t][i];
      f2 = f2 || (j == hl) || (s.A[j][hl] != 0.f);
      e2 = e2 || (j == tl) || (s.A[j][tl] != 0.f);
    }
    s.fh[0][t] = (t == hl) ? 1.f : 0.f;  s.ft[0][t] = (t == tl) ? 1.f : 0.f;
    s.fh[1][t] = f1 ? 1.f : 0.f;         s.ft[1][t] = e1 ? 1.f : 0.f;
    s.fh[2][t] = f2 ? 1.f : 0.f;         s.ft[2][t] = e2 ? 1.f : 0.f;
  }
  __syncthreads();

  // ---------------- P2b: compact task lists per hop (warps 0-2) -------------
  if (w < 3) {
    const unsigned below = (1u << l) - 1u;
    const bool v0 = s.fh[w][l] != 0.f, v1 = s.fh[w][l + 32] != 0.f;
    const unsigned b0 = __ballot_sync(0xFFFFFFFFu, v0);
    const unsigned b1 = __ballot_sync(0xFFFFFFFFu, v1);
    const int nH = __popc(b0) + __popc(b1);
    if (v0) s.tasks[w][__popc(b0 & below)] = (unsigned char)l;
    if (v1) s.tasks[w][__popc(b0) + __popc(b1 & below)] = (unsigned char)(l + 32);
    const bool u0 = s.ft[w][l] != 0.f, u1 = s.ft[w][l + 32] != 0.f;
    const unsigned c0 = __ballot_sync(0xFFFFFFFFu, u0);
    const unsigned c1 = __ballot_sync(0xFFFFFFFFu, u1);
    const int nT = __popc(c0) + __popc(c1);
    if (u0) s.tasks[w][nH + __popc(c0 & below)] = (unsigned char)(64 + l);
    if (u1) s.tasks[w][nH + __popc(c0) + __popc(c1 & below)] = (unsigned char)(64 + l + 32);
    if (l == 0) s.ncnt[w] = nH + nT;
  }
  __syncthreads();

  // ---------------- main loop: it = 0,1,2 (hop = 2,1,0) ---------------------
  for (int it = 0; it < 3; ++it) {
    const int hop = 2 - it;
    const int cnt = s.ncnt[hop];

    // Phase A: out[it] (for it>0), cor + wei for all rows, both sides
    #pragma unroll
    for (int p = 0; p < 2; ++p) {
      const int r = w * 4 + p * 2 + h16;
      const float4 hv = H4[r * 16 + li];
      const float4 tv = T4[r * 16 + li];
      if (it > 0) {
        float4 o = make_float4(hv.x + tv.x, hv.y + tv.y, hv.z + tv.z, hv.w + tv.w);
        *reinterpret_cast<float4*>(out + (size_t)(base + r) * 256 + (size_t)it * 64 + li * 4) = o;
      }
      const float4 q1 = F4[tl * 16 + li];
      float c1 = rsum16(hv.x * q1.x + hv.y * q1.y + hv.z * q1.z + hv.w * q1.w, hm);
      c1 = fabsf(c1);
      WE14[r * 16 + li] = make_float4(c1 * hv.x, c1 * hv.y, c1 * hv.z, c1 * hv.w);
      const float4 q2 = F4[hl * 16 + li];
      float c2 = rsum16(tv.x * q2.x + tv.y * q2.y + tv.z * q2.z + tv.w * q2.w, hm);
      c2 = fabsf(c2);
      WE24[r * 16 + li] = make_float4(c2 * tv.x, c2 * tv.y, c2 * tv.z, c2 * tv.w);
    }
    __syncthreads();

    // Phase B: neighbor-sum aggregation + leaky + /deg + LayerNorm -> U (+F)
    #pragma unroll
    for (int p = 0; p < 2; ++p) {
      for (int t = w * 4 + p * 2 + h16; t < cnt; t += 64) {
        const int v  = s.tasks[hop][t];
        const int sd = v >> 6;
        const int r  = v & 63;
        const float4* WE = sd ? WE24 : WE14;
        const int dg = (int)s.degf[r];
        float4 acc = make_float4(0.f, 0.f, 0.f, 0.f);
        for (int i = 0; i < dg; ++i) {
          const int j = s.nbr[r][i];
          const float4 wv = WE[j * 16 + li];
          acc.x += wv.x; acc.y += wv.y; acc.z += wv.z; acc.w += wv.w;
        }
        acc.x = (acc.x >= 0.f) ? acc.x : 0.01f * acc.x;
        acc.y = (acc.y >= 0.f) ? acc.y : 0.01f * acc.y;
        acc.z = (acc.z >= 0.f) ? acc.z : 0.01f * acc.z;
        acc.w = (acc.w >= 0.f) ? acc.w : 0.01f * acc.w;
        const float inv = 1.f / (s.degf[r] + 1e-8f);
        acc.x *= inv; acc.y *= inv; acc.z *= inv; acc.w *= inv;
        const float mu = rsum16(acc.x + acc.y + acc.z + acc.w, hm) * (1.f / 64.f);
        const float4 d = make_float4(acc.x - mu, acc.y - mu, acc.z - mu, acc.w - mu);
        const float var = rsum16(d.x * d.x + d.y * d.y + d.z * d.z + d.w * d.w, hm) * (1.f / 64.f);
        const float rs = rsqrtf(var + 1e-5f);
        const float4 gg = sd ? g2_4[li]  : g1_4[li];
        const float4 bb = sd ? be2_4[li] : be1_4[li];
        const float4 fv = F4[r * 16 + li];
        float4 u;
        u.x = fv.x + fmaf(gg.x * rs, d.x, bb.x);
        u.y = fv.y + fmaf(gg.y * rs, d.y, bb.y);
        u.z = fv.z + fmaf(gg.z * rs, d.z, bb.z);
        u.w = fv.w + fmaf(gg.w * rs, d.w, bb.w);
        (sd ? U24 : U14)[r * 16 + li] = u;
      }
    }
    __syncthreads();

    // Phase C: H/T[r] = relu(U[r] @ W + b) over compacted tasks
    #pragma unroll
    for (int p = 0; p < 2; ++p) {
      for (int t = w * 4 + p * 2 + h16; t < cnt; t += 64) {
        const int v  = s.tasks[hop][t];
        const int sd = v >> 6;
        const int r  = v & 63;
        const float4* Wp = sd ? W24 : W14;
        const float4* Xp = sd ? U24 : U14;
        float4 acc = sd ? bb2_4[li] : bb1_4[li];
        #pragma unroll
        for (int kb = 0; kb < 16; ++kb) {
          const float4 xv = Xp[r * 16 + kb];
          fma4(acc, xv.x, Wp[(4 * kb + 0) * 16 + li]);
          fma4(acc, xv.y, Wp[(4 * kb + 1) * 16 + li]);
          fma4(acc, xv.z, Wp[(4 * kb + 2) * 16 + li]);
          fma4(acc, xv.w, Wp[(4 * kb + 3) * 16 + li]);
        }
        acc.x = fmaxf(acc.x, 0.f); acc.y = fmaxf(acc.y, 0.f);
        acc.z = fmaxf(acc.z, 0.f); acc.w = fmaxf(acc.w, 0.f);
        (sd ? T4 : H4)[r * 16 + li] = acc;
      }
    }
    __syncthreads();
  }

  // ---------------- final: out layer 3 = H + T -------------------------------
  #pragma unroll
  for (int p = 0; p < 2; ++p) {
    const int r = w * 4 + p * 2 + h16;
    const float4 hv = H4[r * 16 + li];
    const float4 tv = T4[r * 16 + li];
    float4 o = make_float4(hv.x + tv.x, hv.y + tv.y, hv.z + tv.z, hv.w + tv.w);
    *reinterpret_cast<float4*>(out + (size_t)(base + r) * 256 + 192 + li * 4) = o;
  }
}

} // namespace

extern "C" void kernel_launch(void* const* d_in, const int* in_sizes, int n_in,
                              void* d_out, int out_size) {
  const float* adj       = (const float*)d_in[0];
  const float* feat_node = (const float*)d_in[1];
  const int*   idx       = (const int*)  d_in[2];
  const int*   head_ids  = (const int*)  d_in[3];
  const int*   tail_ids  = (const int*)  d_in[4];
  // d_in[5] = graph_indices (implicit in block layout)
  const float* transform = (const float*)d_in[6];
  const float* embed     = (const float*)d_in[7];
  const float* w1        = (const float*)d_in[8];
  const float* b1        = (const float*)d_in[9];
  const float* w2        = (const float*)d_in[10];
  const float* b2        = (const float*)d_in[11];
  const float* gamma1    = (const float*)d_in[12];
  const float* beta1     = (const float*)d_in[13];
  const float* gamma2    = (const float*)d_in[14];
  const float* beta2     = (const float*)d_in[15];
  float* out = (float*)d_out;

  const int smem = (int)sizeof(Smem);
  cudaFuncSetAttribute(lagat_kernel, cudaFuncAttributeMaxDynamicSharedMemorySize, smem);
  lagat_kernel<<<NB, NT, smem>>>(adj, feat_node, idx, head_ids, tail_ids,
                                 transform, embed, w1, b1, w2, b2,
                                 gamma1, beta1, gamma2, beta2, out);
}

// round 3
// speedup vs baseline: 2.0042x; 1.3330x over previous
#include <cuda_runtime.h>

namespace {

constexpr int NB = 64;   // graphs (blocks)
constexpr int NT = 512;  // threads per block (16 warps)

struct Smem {
  float F [64][64];
  float H [64][64];
  float T [64][64];
  float U1[64][64];   // xcat staging, then F + LN-out (head side)
  float U2[64][64];   // F + LN-out (tail side)
  float W1[64][64];
  float W2[64][64];
  float TR[64][64];
  float WE1[64][64];  // cor1[j] * H[j][:]
  float WE2[64][64];  // cor2[j] * T[j][:]
  unsigned m0[64], m1[64];       // adjacency bitmasks (cols 0-31 / 32-63)
  float degf[64];
  float g1[64], be1[64], g2[64], be2[64], bb1[64], bb2[64];
  unsigned frontier[3][2][2];    // [hop][side 0=head,1=tail][word]
  int   cnt[3];
  unsigned char tasks[3][128];   // (side<<6)|row ; head tasks then tail tasks
};

__device__ __forceinline__ float rsum16(float v, unsigned m) {
  v += __shfl_xor_sync(m, v, 8);
  v += __shfl_xor_sync(m, v, 4);
  v += __shfl_xor_sync(m, v, 2);
  v += __shfl_xor_sync(m, v, 1);
  return v;
}

__device__ __forceinline__ void fma4(float4& a, float s, const float4& b) {
  a.x = fmaf(s, b.x, a.x); a.y = fmaf(s, b.y, a.y);
  a.z = fmaf(s, b.z, a.z); a.w = fmaf(s, b.w, a.w);
}
__device__ __forceinline__ void add4(float4& a, const float4& b) {
  a.x += b.x; a.y += b.y; a.z += b.z; a.w += b.w;
}
__device__ __forceinline__ bool bitr(unsigned w0, unsigned w1, int r) {
  return ((r < 32 ? (w0 >> r) : (w1 >> (r - 32))) & 1u) != 0u;
}

__global__ __launch_bounds__(NT, 1)
void lagat_kernel(const float* __restrict__ adj,
                  const float* __restrict__ feat_node,
                  const int*   __restrict__ idx,
                  const int*   __restrict__ head_ids,
                  const int*   __restrict__ tail_ids,
                  const float* __restrict__ transform,
                  const float* __restrict__ embed,
                  const float* __restrict__ w1, const float* __restrict__ b1,
                  const float* __restrict__ w2, const float* __restrict__ b2,
                  const float* __restrict__ gamma1, const float* __restrict__ beta1,
                  const float* __restrict__ gamma2, const float* __restrict__ beta2,
                  float* __restrict__ out)
{
  extern __shared__ float smem_raw[];
  Smem& s = *reinterpret_cast<Smem*>(smem_raw);
  const int g    = blockIdx.x;
  const int tid  = threadIdx.x;
  const int w    = tid >> 5;
  const int l    = tid & 31;
  const int li   = l & 15;
  const int h16  = l >> 4;
  const unsigned hm = (l < 16) ? 0x0000FFFFu : 0xFFFF0000u;
  const int base = g * 64;

  float4* F4   = reinterpret_cast<float4*>(&s.F [0][0]);
  float4* H4   = reinterpret_cast<float4*>(&s.H [0][0]);
  float4* T4   = reinterpret_cast<float4*>(&s.T [0][0]);
  float4* U14  = reinterpret_cast<float4*>(&s.U1[0][0]);
  float4* U24  = reinterpret_cast<float4*>(&s.U2[0][0]);
  float4* W14  = reinterpret_cast<float4*>(&s.W1[0][0]);
  float4* W24  = reinterpret_cast<float4*>(&s.W2[0][0]);
  float4* TR4  = reinterpret_cast<float4*>(&s.TR[0][0]);
  float4* WE14 = reinterpret_cast<float4*>(&s.WE1[0][0]);
  float4* WE24 = reinterpret_cast<float4*>(&s.WE2[0][0]);
  const float4* g1_4  = reinterpret_cast<const float4*>(s.g1);
  const float4* be1_4 = reinterpret_cast<const float4*>(s.be1);
  const float4* g2_4  = reinterpret_cast<const float4*>(s.g2);
  const float4* be2_4 = reinterpret_cast<const float4*>(s.be2);
  const float4* bb1_4 = reinterpret_cast<const float4*>(s.bb1);
  const float4* bb2_4 = reinterpret_cast<const float4*>(s.bb2);

  const int hl = head_ids[g] - base;
  const int tl = tail_ids[g] - base;

  // ---------------- P0: global loads + adjacency bitmask build --------------
  {
    // adjacency: warp w owns rows 4w..4w+3; all 8 LDGs issued before ballots
    float av[4][2];
    #pragma unroll
    for (int rr = 0; rr < 4; ++rr) {
      const float* arow = adj + (size_t)(base + w * 4 + rr) * 4096 + base;
      av[rr][0] = arow[l];
      av[rr][1] = arow[l + 32];
    }
    #pragma unroll
    for (int rr = 0; rr < 4; ++rr) {
      const unsigned b0 = __ballot_sync(0xFFFFFFFFu, av[rr][0] != 0.f);
      const unsigned b1 = __ballot_sync(0xFFFFFFFFu, av[rr][1] != 0.f);
      if (l == 0) {
        const int r = w * 4 + rr;
        s.m0[r] = b0; s.m1[r] = b1;
        s.degf[r] = (float)(__popc(b0) + __popc(b1));
      }
    }
  }
  #pragma unroll
  for (int e = tid; e < 1024; e += NT) {
    TR4[e] = reinterpret_cast<const float4*>(transform)[e];
    W14[e] = reinterpret_cast<const float4*>(w1)[e];
    W24[e] = reinterpret_cast<const float4*>(w2)[e];
  }
  {
    // xcat -> U1: [feat_node(32) | embed[idx](32)]
    const int i = tid >> 3, j = tid & 7;
    U14[i * 16 + j] = *reinterpret_cast<const float4*>(feat_node + (base + i) * 32 + j * 4);
    const int id = idx[base + i];
    U14[i * 16 + 8 + j] = *reinterpret_cast<const float4*>(embed + (size_t)id * 32 + j * 4);
  }
  if (tid < 64) {
    s.g1[tid] = gamma1[tid]; s.be1[tid] = beta1[tid];
    s.g2[tid] = gamma2[tid]; s.be2[tid] = beta2[tid];
    s.bb1[tid] = b1[tid];    s.bb2[tid] = b2[tid];
  }
  __syncthreads();

  // ---------------- P1: feat = xcat @ TR (2-row blocked) + frontier (w0) ----
  {
    const int ra = w * 4 + h16;       // rows ra and ra+2 per half-warp
    const int rb = ra + 2;
    float4 aa = make_float4(0.f, 0.f, 0.f, 0.f);
    float4 ab = make_float4(0.f, 0.f, 0.f, 0.f);
    #pragma unroll
    for (int kb = 0; kb < 16; ++kb) {
      const float4 xa = U14[ra * 16 + kb];
      const float4 xb = U14[rb * 16 + kb];
      float4 wq;
      wq = TR4[(4 * kb + 0) * 16 + li]; fma4(aa, xa.x, wq); fma4(ab, xb.x, wq);
      wq = TR4[(4 * kb + 1) * 16 + li]; fma4(aa, xa.y, wq); fma4(ab, xb.y, wq);
      wq = TR4[(4 * kb + 2) * 16 + li]; fma4(aa, xa.z, wq); fma4(ab, xb.z, wq);
      wq = TR4[(4 * kb + 3) * 16 + li]; fma4(aa, xa.w, wq); fma4(ab, xb.w, wq);
    }
    F4[ra * 16 + li] = aa; H4[ra * 16 + li] = aa; T4[ra * 16 + li] = aa;
    F4[rb * 16 + li] = ab; H4[rb * 16 + li] = ab; T4[rb * 16 + li] = ab;
    *reinterpret_cast<float4*>(out + (size_t)(base + ra) * 256 + li * 4) = aa;
    *reinterpret_cast<float4*>(out + (size_t)(base + rb) * 256 + li * 4) = ab;
  }

  // frontier + task lists: warp 0 only (mask algebra + ballots)
  if (w == 0) {
    const unsigned fh1_0 = s.m0[hl] | (hl < 32 ? 1u << hl : 0u);
    const unsigned fh1_1 = s.m1[hl] | (hl >= 32 ? 1u << (hl - 32) : 0u);
    const unsigned ft1_0 = s.m0[tl] | (tl < 32 ? 1u << tl : 0u);
    const unsigned ft1_1 = s.m1[tl] | (tl >= 32 ? 1u << (tl - 32) : 0u);
    const unsigned ma0 = s.m0[l],      ma1 = s.m1[l];       // row l
    const unsigned mb0 = s.m0[l + 32], mb1 = s.m1[l + 32];  // row l+32
    const bool h2a = bitr(fh1_0, fh1_1, l)      || (ma0 & fh1_0) || (ma1 & fh1_1);
    const bool h2b = bitr(fh1_0, fh1_1, l + 32) || (mb0 & fh1_0) || (mb1 & fh1_1);
    const bool t2a = bitr(ft1_0, ft1_1, l)      || (ma0 & ft1_0) || (ma1 & ft1_1);
    const bool t2b = bitr(ft1_0, ft1_1, l + 32) || (mb0 & ft1_0) || (mb1 & ft1_1);
    const unsigned fh2_0 = __ballot_sync(0xFFFFFFFFu, h2a);
    const unsigned fh2_1 = __ballot_sync(0xFFFFFFFFu, h2b);
    const unsigned ft2_0 = __ballot_sync(0xFFFFFFFFu, t2a);
    const unsigned ft2_1 = __ballot_sync(0xFFFFFFFFu, t2b);
    unsigned hw0[3] = { (hl < 32 ? 1u << hl : 0u), fh1_0, fh2_0 };
    unsigned hw1[3] = { (hl >= 32 ? 1u << (hl - 32) : 0u), fh1_1, fh2_1 };
    unsigned tw0[3] = { (tl < 32 ? 1u << tl : 0u), ft1_0, ft2_0 };
    unsigned tw1[3] = { (tl >= 32 ? 1u << (tl - 32) : 0u), ft1_1, ft2_1 };
    const unsigned below = (1u << l) - 1u;
    #pragma unroll
    for (int hp = 0; hp < 3; ++hp) {
      if (l == 0) {
        s.frontier[hp][0][0] = hw0[hp]; s.frontier[hp][0][1] = hw1[hp];
        s.frontier[hp][1][0] = tw0[hp]; s.frontier[hp][1][1] = tw1[hp];
      }
      const int nH = __popc(hw0[hp]) + __popc(hw1[hp]);
      if ((hw0[hp] >> l) & 1u) s.tasks[hp][__popc(hw0[hp] & below)] = (unsigned char)l;
      if ((hw1[hp] >> l) & 1u) s.tasks[hp][__popc(hw0[hp]) + __popc(hw1[hp] & below)] = (unsigned char)(l + 32);
      if ((tw0[hp] >> l) & 1u) s.tasks[hp][nH + __popc(tw0[hp] & below)] = (unsigned char)(64 + l);
      if ((tw1[hp] >> l) & 1u) s.tasks[hp][nH + __popc(tw0[hp]) + __popc(tw1[hp] & below)] = (unsigned char)(64 + l + 32);
      if (l == 0) s.cnt[hp] = nH + __popc(tw0[hp]) + __popc(tw1[hp]);
    }
  }
  __syncthreads();

  // ---------------- main loop: it = 0,1,2 (hop = 2,1,0) ---------------------
  for (int it = 0; it < 3; ++it) {
    const int hop = 2 - it;
    const int cnt = s.cnt[hop];

    // Phase A: out[it] (for it>0) for all rows; WE for needed rows
    {
      unsigned nh0 = ~0u, nh1 = ~0u, nt0 = ~0u, nt1 = ~0u;
      if (it > 0) {
        nh0 = s.frontier[hop + 1][0][0]; nh1 = s.frontier[hop + 1][0][1];
        nt0 = s.frontier[hop + 1][1][0]; nt1 = s.frontier[hop + 1][1][1];
      }
      const float4 q1 = F4[tl * 16 + li];
      const float4 q2 = F4[hl * 16 + li];
      #pragma unroll
      for (int p = 0; p < 2; ++p) {
        const int r = w * 4 + p * 2 + h16;
        const float4 hv = H4[r * 16 + li];
        const float4 tv = T4[r * 16 + li];
        if (it > 0) {
          float4 o = make_float4(hv.x + tv.x, hv.y + tv.y, hv.z + tv.z, hv.w + tv.w);
          *reinterpret_cast<float4*>(out + (size_t)(base + r) * 256 + (size_t)it * 64 + li * 4) = o;
        }
        if (bitr(nh0, nh1, r)) {
          float c1 = rsum16(hv.x * q1.x + hv.y * q1.y + hv.z * q1.z + hv.w * q1.w, hm);
          c1 = fabsf(c1);
          WE14[r * 16 + li] = make_float4(c1 * hv.x, c1 * hv.y, c1 * hv.z, c1 * hv.w);
        }
        if (bitr(nt0, nt1, r)) {
          float c2 = rsum16(tv.x * q2.x + tv.y * q2.y + tv.z * q2.z + tv.w * q2.w, hm);
          c2 = fabsf(c2);
          WE24[r * 16 + li] = make_float4(c2 * tv.x, c2 * tv.y, c2 * tv.z, c2 * tv.w);
        }
      }
    }
    __syncthreads();

    // Fused Phase B+C over task pairs: each half-warp takes tasks (2t, 2t+1)
    {
      const int hw = w * 2 + h16;   // 0..31
      for (int t2 = hw; 2 * t2 < cnt; t2 += 32) {
        const int ia = 2 * t2;
        const int ib = ia + 1;
        const int va = s.tasks[hop][ia];
        const int vb = (ib < cnt) ? (int)s.tasks[hop][ib] : -1;

        // ---- Phase B for one or two tasks ----
        #pragma unroll
        for (int q = 0; q < 2; ++q) {
          const int v = q ? vb : va;
          if (v < 0) continue;
          const int sd = v >> 6, r = v & 63;
          unsigned mm0 = s.m0[r], mm1 = s.m1[r];
          const float4* WE = sd ? WE24 : WE14;
          float4 acc = make_float4(0.f, 0.f, 0.f, 0.f);
          while (mm0) { const int j = __ffs(mm0) - 1; mm0 &= mm0 - 1; add4(acc, WE[j * 16 + li]); }
          while (mm1) { const int j = __ffs(mm1) + 31; mm1 &= mm1 - 1; add4(acc, WE[j * 16 + li]); }
          acc.x = (acc.x >= 0.f) ? acc.x : 0.01f * acc.x;
          acc.y = (acc.y >= 0.f) ? acc.y : 0.01f * acc.y;
          acc.z = (acc.z >= 0.f) ? acc.z : 0.01f * acc.z;
          acc.w = (acc.w >= 0.f) ? acc.w : 0.01f * acc.w;
          const float inv = 1.f / (s.degf[r] + 1e-8f);
          acc.x *= inv; acc.y *= inv; acc.z *= inv; acc.w *= inv;
          const float mu = rsum16(acc.x + acc.y + acc.z + acc.w, hm) * (1.f / 64.f);
          const float4 d = make_float4(acc.x - mu, acc.y - mu, acc.z - mu, acc.w - mu);
          const float var = rsum16(d.x * d.x + d.y * d.y + d.z * d.z + d.w * d.w, hm) * (1.f / 64.f);
          const float rs = rsqrtf(var + 1e-5f);
          const float4 gg = sd ? g2_4[li]  : g1_4[li];
          const float4 bb = sd ? be2_4[li] : be1_4[li];
          const float4 fv = F4[r * 16 + li];
          float4 u;
          u.x = fv.x + fmaf(gg.x * rs, d.x, bb.x);
          u.y = fv.y + fmaf(gg.y * rs, d.y, bb.y);
          u.z = fv.z + fmaf(gg.z * rs, d.z, bb.z);
          u.w = fv.w + fmaf(gg.w * rs, d.w, bb.w);
          (sd ? U24 : U14)[r * 16 + li] = u;
        }
        __syncwarp(hm);

        // ---- Phase C GEMM: pair share W when same side ----
        if (vb >= 0 && (va >> 6) == (vb >> 6)) {
          const int sd = va >> 6, ra = va & 63, rb = vb & 63;
          const float4* Wp = sd ? W24 : W14;
          const float4* Xp = sd ? U24 : U14;
          float4 aa = sd ? bb2_4[li] : bb1_4[li];
          float4 ab = aa;
          #pragma unroll
          for (int kb = 0; kb < 16; ++kb) {
            const float4 xa = Xp[ra * 16 + kb];
            const float4 xb = Xp[rb * 16 + kb];
            float4 wq;
            wq = Wp[(4 * kb + 0) * 16 + li]; fma4(aa, xa.x, wq); fma4(ab, xb.x, wq);
            wq = Wp[(4 * kb + 1) * 16 + li]; fma4(aa, xa.y, wq); fma4(ab, xb.y, wq);
            wq = Wp[(4 * kb + 2) * 16 + li]; fma4(aa, xa.z, wq); fma4(ab, xb.z, wq);
            wq = Wp[(4 * kb + 3) * 16 + li]; fma4(aa, xa.w, wq); fma4(ab, xb.w, wq);
          }
          aa.x = fmaxf(aa.x, 0.f); aa.y = fmaxf(aa.y, 0.f);
          aa.z = fmaxf(aa.z, 0.f); aa.w = fmaxf(aa.w, 0.f);
          ab.x = fmaxf(ab.x, 0.f); ab.y = fmaxf(ab.y, 0.f);
          ab.z = fmaxf(ab.z, 0.f); ab.w = fmaxf(ab.w, 0.f);
          float4* D = sd ? T4 : H4;
          D[ra * 16 + li] = aa;
          D[rb * 16 + li] = ab;
        } else {
          #pragma unroll
          for (int q = 0; q < 2; ++q) {
            const int v = q ? vb : va;
            if (v < 0) continue;
            const int sd = v >> 6, r = v & 63;
            const float4* Wp = sd ? W24 : W14;
            const float4* Xp = sd ? U24 : U14;
            float4 aa = sd ? bb2_4[li] : bb1_4[li];
            #pragma unroll
            for (int kb = 0; kb < 16; ++kb) {
              const float4 xv = Xp[r * 16 + kb];
              fma4(aa, xv.x, Wp[(4 * kb + 0) * 16 + li]);
              fma4(aa, xv.y, Wp[(4 * kb + 1) * 16 + li]);
              fma4(aa, xv.z, Wp[(4 * kb + 2) * 16 + li]);
              fma4(aa, xv.w, Wp[(4 * kb + 3) * 16 + li]);
            }
            aa.x = fmaxf(aa.x, 0.f); aa.y = fmaxf(aa.y, 0.f);
            aa.z = fmaxf(aa.z, 0.f); aa.w = fmaxf(aa.w, 0.f);
            (sd ? T4 : H4)[r * 16 + li] = aa;
          }
        }
      }
    }
    __syncthreads();
  }

  // ---------------- final: out layer 3 = H + T ------------------------------
  #pragma unroll
  for (int p = 0; p < 2; ++p) {
    const int r = w * 4 + p * 2 + h16;
    const float4 hv = H4[r * 16 + li];
    const float4 tv = T4[r * 16 + li];
    float4 o = make_float4(hv.x + tv.x, hv.y + tv.y, hv.z + tv.z, hv.w + tv.w);
    *reinterpret_cast<float4*>(out + (size_t)(base + r) * 256 + 192 + li * 4) = o;
  }
}

} // namespace

extern "C" void kernel_launch(void* const* d_in, const int* in_sizes, int n_in,
                              void* d_out, int out_size) {
  const float* adj       = (const float*)d_in[0];
  const float* feat_node = (const float*)d_in[1];
  const int*   idx       = (const int*)  d_in[2];
  const int*   head_ids  = (const int*)  d_in[3];
  const int*   tail_ids  = (const int*)  d_in[4];
  // d_in[5] = graph_indices (implicit in block layout)
  const float* transform = (const float*)d_in[6];
  const float* embed     = (const float*)d_in[7];
  const float* w1        = (const float*)d_in[8];
  const float* b1        = (const float*)d_in[9];
  const float* w2        = (const float*)d_in[10];
  const float* b2        = (const float*)d_in[11];
  const float* gamma1    = (const float*)d_in[12];
  const float* beta1     = (const float*)d_in[13];
  const float* gamma2    = (const float*)d_in[14];
  const float* beta2     = (const float*)d_in[15];
  float* out = (float*)d_out;

  const int smem = (int)sizeof(Smem);
  cudaFuncSetAttribute(lagat_kernel, cudaFuncAttributeMaxDynamicSharedMemorySize, smem);
  lagat_kernel<<<NB, NT, smem>>>(adj, feat_node, idx, head_ids, tail_ids,
                                 transform, embed, w1, b1, w2, b2,
                                 gamma1, beta1, gamma2, beta2, out);
}

// round 4
// speedup vs baseline: 2.6566x; 1.3255x over previous
#include <cuda_runtime.h>

namespace {

constexpr int NT = 512;  // threads per CTA (16 warps)

__device__ float g_scratch[64][3][64][64];   // [graph][layer-1][row][col], 3 MB

struct Smem {
  float F [64][64];
  float S [64][64];     // side state: H (side0) or T (side1)
  float U [64][64];     // xcat staging, then F + LN-out
  float W [64][64];     // w1 or w2
  float TR[64][64];
  float WE[64][64];     // cor[j] * S[j][:]
  float SAV[2][64][64]; // side0: saved H layers 1,2
  unsigned m0[64], m1[64];   // adjacency bitmasks
  float degf[64];
  float gmm[64], bet[64], bias[64];
  unsigned fr0[3], fr1[3];   // frontier words per hop
  int   cnt[3];
  unsigned char tasks[3][64];
};

__device__ __forceinline__ float rsum16(float v, unsigned m) {
  v += __shfl_xor_sync(m, v, 8);
  v += __shfl_xor_sync(m, v, 4);
  v += __shfl_xor_sync(m, v, 2);
  v += __shfl_xor_sync(m, v, 1);
  return v;
}
__device__ __forceinline__ void fma4(float4& a, float s, const float4& b) {
  a.x = fmaf(s, b.x, a.x); a.y = fmaf(s, b.y, a.y);
  a.z = fmaf(s, b.z, a.z); a.w = fmaf(s, b.w, a.w);
}
__device__ __forceinline__ void add4(float4& a, const float4& b) {
  a.x += b.x; a.y += b.y; a.z += b.z; a.w += b.w;
}
__device__ __forceinline__ bool bitr(unsigned w0, unsigned w1, int r) {
  return ((r < 32 ? (w0 >> r) : (w1 >> (r - 32))) & 1u) != 0u;
}

__global__ __launch_bounds__(NT, 1) __cluster_dims__(2, 1, 1)
void lagat_kernel(const float* __restrict__ adj,
                  const float* __restrict__ feat_node,
                  const int*   __restrict__ idx,
                  const int*   __restrict__ head_ids,
                  const int*   __restrict__ tail_ids,
                  const float* __restrict__ transform,
                  const float* __restrict__ embed,
                  const float* __restrict__ w1, const float* __restrict__ b1,
                  const float* __restrict__ w2, const float* __restrict__ b2,
                  const float* __restrict__ gamma1, const float* __restrict__ beta1,
                  const float* __restrict__ gamma2, const float* __restrict__ beta2,
                  float* __restrict__ out)
{
  extern __shared__ float smem_raw[];
  Smem& s = *reinterpret_cast<Smem*>(smem_raw);
  const int g    = blockIdx.x >> 1;
  const int side = blockIdx.x & 1;      // 0 = head chain, 1 = tail chain
  const int tid  = threadIdx.x;
  const int w    = tid >> 5;
  const int l    = tid & 31;
  const int li   = l & 15;
  const int h16  = l >> 4;
  const unsigned hm = (l < 16) ? 0x0000FFFFu : 0xFFFF0000u;
  const int base = g * 64;

  float4* F4   = reinterpret_cast<float4*>(&s.F [0][0]);
  float4* S4   = reinterpret_cast<float4*>(&s.S [0][0]);
  float4* U4   = reinterpret_cast<float4*>(&s.U [0][0]);
  float4* W4   = reinterpret_cast<float4*>(&s.W [0][0]);
  float4* TR4  = reinterpret_cast<float4*>(&s.TR[0][0]);
  float4* WE4  = reinterpret_cast<float4*>(&s.WE[0][0]);
  float4* SV4  = reinterpret_cast<float4*>(&s.SAV[0][0][0]);
  const float4* gm4 = reinterpret_cast<const float4*>(s.gmm);
  const float4* bt4 = reinterpret_cast<const float4*>(s.bet);
  const float4* bi4 = reinterpret_cast<const float4*>(s.bias);

  const int hl = head_ids[g] - base;
  const int tl = tail_ids[g] - base;
  const int c_own = side ? tl : hl;   // BFS center for this chain
  const int c_qry = side ? hl : tl;   // query center (opposite)

  const float* Wsrc = side ? w2 : w1;
  const float* Gsrc = side ? gamma2 : gamma1;
  const float* Bsrc = side ? beta2  : beta1;
  const float* bsrc = side ? b2 : b1;

  // ---------------- P0: loads + adjacency bitmask ---------------------------
  {
    float av[4][2];
    #pragma unroll
    for (int rr = 0; rr < 4; ++rr) {
      const float* arow = adj + (size_t)(base + w * 4 + rr) * 4096 + base;
      av[rr][0] = arow[l];
      av[rr][1] = arow[l + 32];
    }
    #pragma unroll
    for (int rr = 0; rr < 4; ++rr) {
      const unsigned b0 = __ballot_sync(0xFFFFFFFFu, av[rr][0] != 0.f);
      const unsigned b1 = __ballot_sync(0xFFFFFFFFu, av[rr][1] != 0.f);
      if (l == 0) {
        const int r = w * 4 + rr;
        s.m0[r] = b0; s.m1[r] = b1;
        s.degf[r] = (float)(__popc(b0) + __popc(b1));
      }
    }
  }
  #pragma unroll
  for (int e = tid; e < 1024; e += NT) {
    TR4[e] = reinterpret_cast<const float4*>(transform)[e];
    W4[e]  = reinterpret_cast<const float4*>(Wsrc)[e];
  }
  {
    const int i = tid >> 3, j = tid & 7;
    U4[i * 16 + j] = *reinterpret_cast<const float4*>(feat_node + (base + i) * 32 + j * 4);
    const int id = idx[base + i];
    U4[i * 16 + 8 + j] = *reinterpret_cast<const float4*>(embed + (size_t)id * 32 + j * 4);
  }
  if (tid < 64) {
    s.gmm[tid] = Gsrc[tid]; s.bet[tid] = Bsrc[tid]; s.bias[tid] = bsrc[tid];
  }
  __syncthreads();

  // ---------------- P1: F = xcat @ TR (2-row blocked); side0 emits layer0 ---
  {
    const int ra = w * 4 + h16;
    const int rb = ra + 2;
    float4 aa = make_float4(0.f, 0.f, 0.f, 0.f);
    float4 ab = make_float4(0.f, 0.f, 0.f, 0.f);
    #pragma unroll
    for (int kb = 0; kb < 16; ++kb) {
      const float4 xa = U4[ra * 16 + kb];
      const float4 xb = U4[rb * 16 + kb];
      float4 wq;
      wq = TR4[(4 * kb + 0) * 16 + li]; fma4(aa, xa.x, wq); fma4(ab, xb.x, wq);
      wq = TR4[(4 * kb + 1) * 16 + li]; fma4(aa, xa.y, wq); fma4(ab, xb.y, wq);
      wq = TR4[(4 * kb + 2) * 16 + li]; fma4(aa, xa.z, wq); fma4(ab, xb.z, wq);
      wq = TR4[(4 * kb + 3) * 16 + li]; fma4(aa, xa.w, wq); fma4(ab, xb.w, wq);
    }
    F4[ra * 16 + li] = aa; S4[ra * 16 + li] = aa;
    F4[rb * 16 + li] = ab; S4[rb * 16 + li] = ab;
    if (side == 0) {
      *reinterpret_cast<float4*>(out + (size_t)(base + ra) * 256 + li * 4) = aa;
      *reinterpret_cast<float4*>(out + (size_t)(base + rb) * 256 + li * 4) = ab;
    }
  }

  // ---------------- frontier + task lists for c_own (warp 0) ----------------
  if (w == 0) {
    const unsigned c0bit = (c_own < 32) ? 1u << c_own : 0u;
    const unsigned c1bit = (c_own >= 32) ? 1u << (c_own - 32) : 0u;
    const unsigned f1_0 = s.m0[c_own] | c0bit;
    const unsigned f1_1 = s.m1[c_own] | c1bit;
    const bool a2 = bitr(f1_0, f1_1, l)      || (s.m0[l] & f1_0)      || (s.m1[l] & f1_1);
    const bool b2 = bitr(f1_0, f1_1, l + 32) || (s.m0[l + 32] & f1_0) || (s.m1[l + 32] & f1_1);
    const unsigned f2_0 = __ballot_sync(0xFFFFFFFFu, a2);
    const unsigned f2_1 = __ballot_sync(0xFFFFFFFFu, b2);
    unsigned fw0[3] = { c0bit, f1_0, f2_0 };
    unsigned fw1[3] = { c1bit, f1_1, f2_1 };
    const unsigned below = (1u << l) - 1u;
    #pragma unroll
    for (int hp = 0; hp < 3; ++hp) {
      if (l == 0) { s.fr0[hp] = fw0[hp]; s.fr1[hp] = fw1[hp]; }
      if ((fw0[hp] >> l) & 1u) s.tasks[hp][__popc(fw0[hp] & below)] = (unsigned char)l;
      if ((fw1[hp] >> l) & 1u) s.tasks[hp][__popc(fw0[hp]) + __popc(fw1[hp] & below)] = (unsigned char)(l + 32);
      if (l == 0) s.cnt[hp] = __popc(fw0[hp]) + __popc(fw1[hp]);
    }
  }
  __syncthreads();

  // ---------------- main loop: it = 0,1,2 (hop = 2,1,0) ---------------------
  for (int it = 0; it < 3; ++it) {
    const int hop = 2 - it;
    const int cnt = s.cnt[hop];

    // Phase A: save/emit layer `it` state; WE for needed rows
    {
      unsigned nb0 = ~0u, nb1 = ~0u;
      if (it > 0) { nb0 = s.fr0[hop + 1]; nb1 = s.fr1[hop + 1]; }
      const float4 q = F4[c_qry * 16 + li];
      #pragma unroll
      for (int p = 0; p < 2; ++p) {
        const int r = w * 4 + p * 2 + h16;
        const float4 sv = S4[r * 16 + li];
        if (it > 0) {
          if (side == 0) SV4[(it - 1) * 1024 + r * 16 + li] = sv;
          else *reinterpret_cast<float4*>(&g_scratch[g][it - 1][r][li * 4]) = sv;
        }
        if (bitr(nb0, nb1, r)) {
          float c = rsum16(sv.x * q.x + sv.y * q.y + sv.z * q.z + sv.w * q.w, hm);
          c = fabsf(c);
          WE4[r * 16 + li] = make_float4(c * sv.x, c * sv.y, c * sv.z, c * sv.w);
        }
      }
    }
    __syncthreads();

    // Fused Phase B+C over task pairs (all tasks same side now)
    {
      const int hw = w * 2 + h16;
      for (int t2 = hw; 2 * t2 < cnt; t2 += 32) {
        const int ia = 2 * t2;
        const int ib = ia + 1;
        const int ra = s.tasks[hop][ia];
        const int rb = (ib < cnt) ? (int)s.tasks[hop][ib] : -1;

        #pragma unroll
        for (int qq = 0; qq < 2; ++qq) {
          const int r = qq ? rb : ra;
          if (r < 0) continue;
          unsigned mm0 = s.m0[r], mm1 = s.m1[r];
          float4 acc = make_float4(0.f, 0.f, 0.f, 0.f);
          while (mm0) { const int j = __ffs(mm0) - 1;  mm0 &= mm0 - 1; add4(acc, WE4[j * 16 + li]); }
          while (mm1) { const int j = __ffs(mm1) + 31; mm1 &= mm1 - 1; add4(acc, WE4[j * 16 + li]); }
          acc.x = (acc.x >= 0.f) ? acc.x : 0.01f * acc.x;
          acc.y = (acc.y >= 0.f) ? acc.y : 0.01f * acc.y;
          acc.z = (acc.z >= 0.f) ? acc.z : 0.01f * acc.z;
          acc.w = (acc.w >= 0.f) ? acc.w : 0.01f * acc.w;
          const float inv = 1.f / (s.degf[r] + 1e-8f);
          acc.x *= inv; acc.y *= inv; acc.z *= inv; acc.w *= inv;
          const float mu = rsum16(acc.x + acc.y + acc.z + acc.w, hm) * (1.f / 64.f);
          const float4 d = make_float4(acc.x - mu, acc.y - mu, acc.z - mu, acc.w - mu);
          const float var = rsum16(d.x * d.x + d.y * d.y + d.z * d.z + d.w * d.w, hm) * (1.f / 64.f);
          const float rs = rsqrtf(var + 1e-5f);
          const float4 gg = gm4[li];
          const float4 bb = bt4[li];
          const float4 fv = F4[r * 16 + li];
          float4 u;
          u.x = fv.x + fmaf(gg.x * rs, d.x, bb.x);
          u.y = fv.y + fmaf(gg.y * rs, d.y, bb.y);
          u.z = fv.z + fmaf(gg.z * rs, d.z, bb.z);
          u.w = fv.w + fmaf(gg.w * rs, d.w, bb.w);
          U4[r * 16 + li] = u;
        }
        __syncwarp(hm);

        if (rb >= 0) {
          float4 aa = bi4[li], ab = bi4[li];
          #pragma unroll
          for (int kb = 0; kb < 16; ++kb) {
            const float4 xa = U4[ra * 16 + kb];
            const float4 xb = U4[rb * 16 + kb];
            float4 wq;
            wq = W4[(4 * kb + 0) * 16 + li]; fma4(aa, xa.x, wq); fma4(ab, xb.x, wq);
            wq = W4[(4 * kb + 1) * 16 + li]; fma4(aa, xa.y, wq); fma4(ab, xb.y, wq);
            wq = W4[(4 * kb + 2) * 16 + li]; fma4(aa, xa.z, wq); fma4(ab, xb.z, wq);
            wq = W4[(4 * kb + 3) * 16 + li]; fma4(aa, xa.w, wq); fma4(ab, xb.w, wq);
          }
          aa.x = fmaxf(aa.x, 0.f); aa.y = fmaxf(aa.y, 0.f);
          aa.z = fmaxf(aa.z, 0.f); aa.w = fmaxf(aa.w, 0.f);
          ab.x = fmaxf(ab.x, 0.f); ab.y = fmaxf(ab.y, 0.f);
          ab.z = fmaxf(ab.z, 0.f); ab.w = fmaxf(ab.w, 0.f);
          S4[ra * 16 + li] = aa;
          S4[rb * 16 + li] = ab;
        } else {
          float4 aa = bi4[li];
          #pragma unroll
          for (int kb = 0; kb < 16; ++kb) {
            const float4 xv = U4[ra * 16 + kb];
            fma4(aa, xv.x, W4[(4 * kb + 0) * 16 + li]);
            fma4(aa, xv.y, W4[(4 * kb + 1) * 16 + li]);
            fma4(aa, xv.z, W4[(4 * kb + 2) * 16 + li]);
            fma4(aa, xv.w, W4[(4 * kb + 3) * 16 + li]);
          }
          aa.x = fmaxf(aa.x, 0.f); aa.y = fmaxf(aa.y, 0.f);
          aa.z = fmaxf(aa.z, 0.f); aa.w = fmaxf(aa.w, 0.f);
          S4[ra * 16 + li] = aa;
        }
      }
    }
    __syncthreads();
  }

  // ---------------- tail: side1 publishes layer3; sync; side0 emits ---------
  if (side == 1) {
    #pragma unroll
    for (int e = tid; e < 1024; e += NT) {
      const int r = e >> 4, c4 = e & 15;
      *reinterpret_cast<float4*>(&g_scratch[g][2][r][c4 * 4]) = S4[e];
    }
    __threadfence();
  }
  asm volatile("barrier.cluster.arrive.aligned;" ::: "memory");
  asm volatile("barrier.cluster.wait.aligned;" ::: "memory");

  if (side == 0) {
    #pragma unroll
    for (int lay = 0; lay < 3; ++lay) {
      #pragma unroll
      for (int e = tid; e < 1024; e += NT) {
        const int r = e >> 4, c4 = e & 15;
        float4 a = (lay < 2) ? SV4[lay * 1024 + e] : S4[e];
        const float4 b = *reinterpret_cast<const float4*>(&g_scratch[g][lay][r][c4 * 4]);
        add4(a, b);
        *reinterpret_cast<float4*>(out + (size_t)(base + r) * 256 + (size_t)(lay + 1) * 64 + c4 * 4) = a;
      }
    }
  }
}

} // namespace

extern "C" void kernel_launch(void* const* d_in, const int* in_sizes, int n_in,
                              void* d_out, int out_size) {
  const float* adj       = (const float*)d_in[0];
  const float* feat_node = (const float*)d_in[1];
  const int*   idx       = (const int*)  d_in[2];
  const int*   head_ids  = (const int*)  d_in[3];
  const int*   tail_ids  = (const int*)  d_in[4];
  // d_in[5] = graph_indices (implicit in block layout)
  const float* transform = (const float*)d_in[6];
  const float* embed     = (const float*)d_in[7];
  const float* w1        = (const float*)d_in[8];
  const float* b1        = (const float*)d_in[9];
  const float* w2        = (const float*)d_in[10];
  const float* b2        = (const float*)d_in[11];
  const float* gamma1    = (const float*)d_in[12];
  const float* beta1     = (const float*)d_in[13];
  const float* gamma2    = (const float*)d_in[14];
  const float* beta2     = (const float*)d_in[15];
  float* out = (float*)d_out;

  const int smem = (int)sizeof(Smem);
  cudaFuncSetAttribute(lagat_kernel, cudaFuncAttributeMaxDynamicSharedMemorySize, smem);
  lagat_kernel<<<128, NT, smem>>>(adj, feat_node, idx, head_ids, tail_ids,
                                  transform, embed, w1, b1, w2, b2,
                                  gamma1, beta1, gamma2, beta2, out);
}

// round 5
// speedup vs baseline: 2.7280x; 1.0269x over previous
#include <cuda_runtime.h>
#include <cstdint>

namespace {

constexpr int NT = 512;  // threads per CTA (16 warps)

struct Smem {
  float F [64][64];
  float S [64][64];      // side state: H (side0) or T (side1)
  float U [64][64];      // xcat staging, then F + LN-out
  float W [64][64];      // w1 or w2
  float TR[64][64];      // transform; reused as Phase-C partial scratch
  float WE[64][64];      // cor[j] * S[j][:]
  float SAV[2][64][64];  // saved S layers 1,2 (all rows)
  unsigned m0[64], m1[64];   // adjacency bitmasks
  float degf[64];
  float gmm[64], bet[64], bias[64];
  unsigned fr0[4], fr1[4];   // frontier words per hop 0..3
  int   cnt[3];
  unsigned char tasks[3][64];
};

__device__ __forceinline__ float rsum16(float v, unsigned m) {
  v += __shfl_xor_sync(m, v, 8);
  v += __shfl_xor_sync(m, v, 4);
  v += __shfl_xor_sync(m, v, 2);
  v += __shfl_xor_sync(m, v, 1);
  return v;
}
__device__ __forceinline__ void fma4(float4& a, float s, const float4& b) {
  a.x = fmaf(s, b.x, a.x); a.y = fmaf(s, b.y, a.y);
  a.z = fmaf(s, b.z, a.z); a.w = fmaf(s, b.w, a.w);
}
__device__ __forceinline__ void add4(float4& a, const float4& b) {
  a.x += b.x; a.y += b.y; a.z += b.z; a.w += b.w;
}
__device__ __forceinline__ void relu4(float4& a) {
  a.x = fmaxf(a.x, 0.f); a.y = fmaxf(a.y, 0.f);
  a.z = fmaxf(a.z, 0.f); a.w = fmaxf(a.w, 0.f);
}
__device__ __forceinline__ bool bitr(unsigned w0, unsigned w1, int r) {
  return ((r < 32 ? (w0 >> r) : (w1 >> (r - 32))) & 1u) != 0u;
}
__device__ __forceinline__ uint32_t smem_u32(const void* p) {
  uint32_t a;
  asm("{ .reg .u64 t; cvta.to.shared.u64 t, %1; cvt.u32.u64 %0, t; }" : "=r"(a) : "l"(p));
  return a;
}
__device__ __forceinline__ uint32_t mapa_u32(uint32_t addr, uint32_t rank) {
  uint32_t r;
  asm("mapa.shared::cluster.u32 %0, %1, %2;" : "=r"(r) : "r"(addr), "r"(rank));
  return r;
}
__device__ __forceinline__ float4 ld_ds4(uint32_t addr) {
  uint32_t a, b, c, d;
  asm volatile("ld.shared::cluster.v4.b32 {%0,%1,%2,%3}, [%4];"
               : "=r"(a), "=r"(b), "=r"(c), "=r"(d) : "r"(addr));
  float4 v;
  v.x = __uint_as_float(a); v.y = __uint_as_float(b);
  v.z = __uint_as_float(c); v.w = __uint_as_float(d);
  return v;
}
#define CLUSTER_SYNC_() do { \
  asm volatile("barrier.cluster.arrive.aligned;" ::: "memory"); \
  asm volatile("barrier.cluster.wait.aligned;"   ::: "memory"); \
} while (0)

__global__ __launch_bounds__(NT, 1) __cluster_dims__(2, 1, 1)
void lagat_kernel(const float* __restrict__ adj,
                  const float* __restrict__ feat_node,
                  const int*   __restrict__ idx,
                  const int*   __restrict__ head_ids,
                  const int*   __restrict__ tail_ids,
                  const float* __restrict__ transform,
                  const float* __restrict__ embed,
                  const float* __restrict__ w1, const float* __restrict__ b1,
                  const float* __restrict__ w2, const float* __restrict__ b2,
                  const float* __restrict__ gamma1, const float* __restrict__ beta1,
                  const float* __restrict__ gamma2, const float* __restrict__ beta2,
                  float* __restrict__ out)
{
  extern __shared__ float smem_raw[];
  Smem& s = *reinterpret_cast<Smem*>(smem_raw);
  const int g    = blockIdx.x >> 1;
  const int side = blockIdx.x & 1;      // 0 = head chain, 1 = tail chain
  const int tid  = threadIdx.x;
  const int w    = tid >> 5;
  const int l    = tid & 31;
  const int li   = l & 15;
  const int h16  = l >> 4;
  const int hw   = w * 2 + h16;         // half-warp id 0..31
  const unsigned hm = (l < 16) ? 0x0000FFFFu : 0xFFFF0000u;
  const int base = g * 64;

  float4* F4  = reinterpret_cast<float4*>(&s.F [0][0]);
  float4* S4  = reinterpret_cast<float4*>(&s.S [0][0]);
  float4* U4  = reinterpret_cast<float4*>(&s.U [0][0]);
  float4* W4  = reinterpret_cast<float4*>(&s.W [0][0]);
  float4* TR4 = reinterpret_cast<float4*>(&s.TR[0][0]);
  float4* P4  = TR4;                    // Phase-C partial scratch (TR dead after P1)
  float4* WE4 = reinterpret_cast<float4*>(&s.WE[0][0]);
  float4* SV4 = reinterpret_cast<float4*>(&s.SAV[0][0][0]);
  const float4* gm4 = reinterpret_cast<const float4*>(s.gmm);
  const float4* bt4 = reinterpret_cast<const float4*>(s.bet);
  const float4* bi4 = reinterpret_cast<const float4*>(s.bias);

  const uint32_t sbase   = smem_u32(&s);
  const uint32_t off_F   = (uint32_t)((const char*)&s.F[0][0]      - (const char*)&s);
  const uint32_t off_S   = (uint32_t)((const char*)&s.S[0][0]      - (const char*)&s);
  const uint32_t off_SAV = (uint32_t)((const char*)&s.SAV[0][0][0] - (const char*)&s);
  const uint32_t pbase   = mapa_u32(sbase, (uint32_t)(side ^ 1));

  const int hl = head_ids[g] - base;
  const int tl = tail_ids[g] - base;
  const int c_own = side ? tl : hl;   // BFS center for this chain
  const int c_qry = side ? hl : tl;   // query center (opposite)

  const float* Wsrc = side ? w2 : w1;
  const float* Gsrc = side ? gamma2 : gamma1;
  const float* Bsrc = side ? beta2  : beta1;
  const float* bsrc = side ? b2 : b1;

  // ---------------- P0: loads + adjacency bitmask ---------------------------
  {
    float av[4][2];
    #pragma unroll
    for (int rr = 0; rr < 4; ++rr) {
      const float* arow = adj + (size_t)(base + w * 4 + rr) * 4096 + base;
      av[rr][0] = arow[l];
      av[rr][1] = arow[l + 32];
    }
    #pragma unroll
    for (int rr = 0; rr < 4; ++rr) {
      const unsigned b0 = __ballot_sync(0xFFFFFFFFu, av[rr][0] != 0.f);
      const unsigned b1 = __ballot_sync(0xFFFFFFFFu, av[rr][1] != 0.f);
      if (l == 0) {
        const int r = w * 4 + rr;
        s.m0[r] = b0; s.m1[r] = b1;
        s.degf[r] = (float)(__popc(b0) + __popc(b1));
      }
    }
  }
  #pragma unroll
  for (int e = tid; e < 1024; e += NT) {
    TR4[e] = reinterpret_cast<const float4*>(transform)[e];
    W4[e]  = reinterpret_cast<const float4*>(Wsrc)[e];
  }
  {
    const int i = tid >> 3, j = tid & 7;
    U4[i * 16 + j] = *reinterpret_cast<const float4*>(feat_node + (base + i) * 32 + j * 4);
    const int id = idx[base + i];
    U4[i * 16 + 8 + j] = *reinterpret_cast<const float4*>(embed + (size_t)id * 32 + j * 4);
  }
  if (tid < 64) {
    s.gmm[tid] = Gsrc[tid]; s.bet[tid] = Bsrc[tid]; s.bias[tid] = bsrc[tid];
  }
  __syncthreads();

  // ---------------- P1: F rows of OWN half only (1 row per half-warp) -------
  {
    const int r = side * 32 + hw;
    float4 acc = make_float4(0.f, 0.f, 0.f, 0.f);
    #pragma unroll
    for (int kb = 0; kb < 16; ++kb) {
      const float4 xv = U4[r * 16 + kb];
      fma4(acc, xv.x, TR4[(4 * kb + 0) * 16 + li]);
      fma4(acc, xv.y, TR4[(4 * kb + 1) * 16 + li]);
      fma4(acc, xv.z, TR4[(4 * kb + 2) * 16 + li]);
      fma4(acc, xv.w, TR4[(4 * kb + 3) * 16 + li]);
    }
    F4[r * 16 + li] = acc;
    S4[r * 16 + li] = acc;
    // layer-0 emission for own half
    *reinterpret_cast<float4*>(out + (size_t)(base + r) * 256 + li * 4) = acc;
  }

  // ---------------- frontier masks (hops 0..3) + task lists (warp 0) --------
  if (w == 0) {
    const unsigned c0bit = (c_own < 32) ? 1u << c_own : 0u;
    const unsigned c1bit = (c_own >= 32) ? 1u << (c_own - 32) : 0u;
    const unsigned f1_0 = s.m0[c_own] | c0bit;
    const unsigned f1_1 = s.m1[c_own] | c1bit;
    const bool a2 = bitr(f1_0, f1_1, l)      || (s.m0[l] & f1_0)      || (s.m1[l] & f1_1);
    const bool b2 = bitr(f1_0, f1_1, l + 32) || (s.m0[l + 32] & f1_0) || (s.m1[l + 32] & f1_1);
    const unsigned f2_0 = __ballot_sync(0xFFFFFFFFu, a2);
    const unsigned f2_1 = __ballot_sync(0xFFFFFFFFu, b2);
    const bool a3 = bitr(f2_0, f2_1, l)      || (s.m0[l] & f2_0)      || (s.m1[l] & f2_1);
    const bool b3 = bitr(f2_0, f2_1, l + 32) || (s.m0[l + 32] & f2_0) || (s.m1[l + 32] & f2_1);
    const unsigned f3_0 = __ballot_sync(0xFFFFFFFFu, a3);
    const unsigned f3_1 = __ballot_sync(0xFFFFFFFFu, b3);
    unsigned fw0[4] = { c0bit, f1_0, f2_0, f3_0 };
    unsigned fw1[4] = { c1bit, f1_1, f2_1, f3_1 };
    const unsigned below = (1u << l) - 1u;
    #pragma unroll
    for (int hp = 0; hp < 4; ++hp) {
      if (l == 0) { s.fr0[hp] = fw0[hp]; s.fr1[hp] = fw1[hp]; }
      if (hp < 3) {
        if ((fw0[hp] >> l) & 1u) s.tasks[hp][__popc(fw0[hp] & below)] = (unsigned char)l;
        if ((fw1[hp] >> l) & 1u) s.tasks[hp][__popc(fw0[hp]) + __popc(fw1[hp] & below)] = (unsigned char)(l + 32);
        if (l == 0) s.cnt[hp] = __popc(fw0[hp]) + __popc(fw1[hp]);
      }
    }
  }

  // ---------------- exchange F halves via DSMEM -----------------------------
  CLUSTER_SYNC_();
  {
    const int r = (side ^ 1) * 32 + (tid >> 4), c4 = tid & 15;   // 512 threads = 32 rows x 16
    const float4 v = ld_ds4(pbase + off_F + (uint32_t)(r * 16 + c4) * 16u);
    F4[r * 16 + c4] = v;
    S4[r * 16 + c4] = v;
  }
  __syncthreads();

  // ---------------- main loop: it = 0,1,2 (hop = 2,1,0) ---------------------
  for (int it = 0; it < 3; ++it) {
    const int hop = 2 - it;
    const int cnt = s.cnt[hop];

    // Phase A: save layer-`it` state (it>0); WE for rows in fr[hop+1]
    {
      const unsigned nb0 = s.fr0[hop + 1], nb1 = s.fr1[hop + 1];
      const float4 q = F4[c_qry * 16 + li];
      #pragma unroll
      for (int p = 0; p < 2; ++p) {
        const int r = w * 4 + p * 2 + h16;
        const float4 sv = S4[r * 16 + li];
        if (it > 0) SV4[(it - 1) * 1024 + r * 16 + li] = sv;
        if (bitr(nb0, nb1, r)) {
          float c = rsum16(sv.x * q.x + sv.y * q.y + sv.z * q.z + sv.w * q.w, hm);
          c = fabsf(c);
          WE4[r * 16 + li] = make_float4(c * sv.x, c * sv.y, c * sv.z, c * sv.w);
        }
      }
    }
    __syncthreads();

    if (cnt > 32) {
      // ---- big path: fused B+C, 2 tasks per half-warp, shared W reads ----
      for (int t2 = hw; 2 * t2 < cnt; t2 += 32) {
        const int ia = 2 * t2;
        const int ib = ia + 1;
        const int ra = s.tasks[hop][ia];
        const int rb = (ib < cnt) ? (int)s.tasks[hop][ib] : -1;

        #pragma unroll
        for (int qq = 0; qq < 2; ++qq) {
          const int r = qq ? rb : ra;
          if (r < 0) continue;
          unsigned mm0 = s.m0[r], mm1 = s.m1[r];
          float4 a0 = make_float4(0.f, 0.f, 0.f, 0.f);
          float4 a1 = make_float4(0.f, 0.f, 0.f, 0.f);
          while (mm0) { const int j = __ffs(mm0) - 1;  mm0 &= mm0 - 1; add4(a0, WE4[j * 16 + li]); }
          while (mm1) { const int j = __ffs(mm1) + 31; mm1 &= mm1 - 1; add4(a1, WE4[j * 16 + li]); }
          add4(a0, a1);
          a0.x = (a0.x >= 0.f) ? a0.x : 0.01f * a0.x;
          a0.y = (a0.y >= 0.f) ? a0.y : 0.01f * a0.y;
          a0.z = (a0.z >= 0.f) ? a0.z : 0.01f * a0.z;
          a0.w = (a0.w >= 0.f) ? a0.w : 0.01f * a0.w;
          const float inv = 1.f / (s.degf[r] + 1e-8f);
          a0.x *= inv; a0.y *= inv; a0.z *= inv; a0.w *= inv;
          const float mu = rsum16(a0.x + a0.y + a0.z + a0.w, hm) * (1.f / 64.f);
          const float4 d = make_float4(a0.x - mu, a0.y - mu, a0.z - mu, a0.w - mu);
          const float var = rsum16(d.x * d.x + d.y * d.y + d.z * d.z + d.w * d.w, hm) * (1.f / 64.f);
          const float rs = rsqrtf(var + 1e-5f);
          const float4 gg = gm4[li];
          const float4 bb = bt4[li];
          const float4 fv = F4[r * 16 + li];
          float4 u;
          u.x = fv.x + fmaf(gg.x * rs, d.x, bb.x);
          u.y = fv.y + fmaf(gg.y * rs, d.y, bb.y);
          u.z = fv.z + fmaf(gg.z * rs, d.z, bb.z);
          u.w = fv.w + fmaf(gg.w * rs, d.w, bb.w);
          U4[r * 16 + li] = u;
        }
        __syncwarp(hm);

        if (rb >= 0) {
          float4 aa = bi4[li], ab = bi4[li];
          #pragma unroll
          for (int kb = 0; kb < 16; ++kb) {
            const float4 xa = U4[ra * 16 + kb];
            const float4 xb = U4[rb * 16 + kb];
            float4 wq;
            wq = W4[(4 * kb + 0) * 16 + li]; fma4(aa, xa.x, wq); fma4(ab, xb.x, wq);
            wq = W4[(4 * kb + 1) * 16 + li]; fma4(aa, xa.y, wq); fma4(ab, xb.y, wq);
            wq = W4[(4 * kb + 2) * 16 + li]; fma4(aa, xa.z, wq); fma4(ab, xb.z, wq);
            wq = W4[(4 * kb + 3) * 16 + li]; fma4(aa, xa.w, wq); fma4(ab, xb.w, wq);
          }
          relu4(aa); relu4(ab);
          S4[ra * 16 + li] = aa;
          S4[rb * 16 + li] = ab;
        } else {
          float4 aa = bi4[li];
          #pragma unroll
          for (int kb = 0; kb < 16; ++kb) {
            const float4 xv = U4[ra * 16 + kb];
            fma4(aa, xv.x, W4[(4 * kb + 0) * 16 + li]);
            fma4(aa, xv.y, W4[(4 * kb + 1) * 16 + li]);
            fma4(aa, xv.z, W4[(4 * kb + 2) * 16 + li]);
            fma4(aa, xv.w, W4[(4 * kb + 3) * 16 + li]);
          }
          relu4(aa);
          S4[ra * 16 + li] = aa;
        }
      }
      __syncthreads();
    } else {
      // ---- small path: B one-task-per-half-warp, then k-split C ----
      int ks_sh = 0;
      if      (cnt <= 2)  ks_sh = 4;
      else if (cnt <= 4)  ks_sh = 3;
      else if (cnt <= 8)  ks_sh = 2;
      else if (cnt <= 16) ks_sh = 1;

      if (hw < cnt) {
        const int r = s.tasks[hop][hw];
        unsigned mm0 = s.m0[r], mm1 = s.m1[r];
        float4 a0 = make_float4(0.f, 0.f, 0.f, 0.f);
        float4 a1 = make_float4(0.f, 0.f, 0.f, 0.f);
        while (mm0) { const int j = __ffs(mm0) - 1;  mm0 &= mm0 - 1; add4(a0, WE4[j * 16 + li]); }
        while (mm1) { const int j = __ffs(mm1) + 31; mm1 &= mm1 - 1; add4(a1, WE4[j * 16 + li]); }
        add4(a0, a1);
        a0.x = (a0.x >= 0.f) ? a0.x : 0.01f * a0.x;
        a0.y = (a0.y >= 0.f) ? a0.y : 0.01f * a0.y;
        a0.z = (a0.z >= 0.f) ? a0.z : 0.01f * a0.z;
        a0.w = (a0.w >= 0.f) ? a0.w : 0.01f * a0.w;
        const float inv = 1.f / (s.degf[r] + 1e-8f);
        a0.x *= inv; a0.y *= inv; a0.z *= inv; a0.w *= inv;
        const float mu = rsum16(a0.x + a0.y + a0.z + a0.w, hm) * (1.f / 64.f);
        const float4 d = make_float4(a0.x - mu, a0.y - mu, a0.z - mu, a0.w - mu);
        const float var = rsum16(d.x * d.x + d.y * d.y + d.z * d.z + d.w * d.w, hm) * (1.f / 64.f);
        const float rs = rsqrtf(var + 1e-5f);
        const float4 gg = gm4[li];
        const float4 bb = bt4[li];
        const float4 fv = F4[r * 16 + li];
        float4 u;
        u.x = fv.x + fmaf(gg.x * rs, d.x, bb.x);
        u.y = fv.y + fmaf(gg.y * rs, d.y, bb.y);
        u.z = fv.z + fmaf(gg.z * rs, d.z, bb.z);
        u.w = fv.w + fmaf(gg.w * rs, d.w, bb.w);
        U4[r * 16 + li] = u;
      }
      __syncthreads();

      // C slices: nslots = cnt * KS half-warps, each covers 16>>ks_sh kb-blocks
      const int KS = 1 << ks_sh;
      const int nslots = cnt << ks_sh;
      if (hw < nslots) {
        const int t  = hw >> ks_sh;
        const int q  = hw & (KS - 1);
        const int r  = s.tasks[hop][t];
        const int nkb = 16 >> ks_sh;
        const int kb0 = q * nkb;
        float4 acc = (ks_sh == 0) ? bi4[li] : make_float4(0.f, 0.f, 0.f, 0.f);
        #pragma unroll 4
        for (int kb = kb0; kb < kb0 + nkb; ++kb) {
          const float4 xv = U4[r * 16 + kb];
          fma4(acc, xv.x, W4[(4 * kb + 0) * 16 + li]);
          fma4(acc, xv.y, W4[(4 * kb + 1) * 16 + li]);
          fma4(acc, xv.z, W4[(4 * kb + 2) * 16 + li]);
          fma4(acc, xv.w, W4[(4 * kb + 3) * 16 + li]);
        }
        if (ks_sh == 0) { relu4(acc); S4[r * 16 + li] = acc; }
        else            P4[hw * 16 + li] = acc;
      }
      __syncthreads();

      if (ks_sh > 0) {
        if (hw < cnt) {
          const int r = s.tasks[hop][hw];
          float4 acc = bi4[li];
          for (int q = 0; q < KS; ++q) add4(acc, P4[((hw << ks_sh) + q) * 16 + li]);
          relu4(acc);
          S4[r * 16 + li] = acc;
        }
        __syncthreads();
      }
    }
  }

  // ---------------- symmetric tail: each side emits its half via DSMEM ------
  CLUSTER_SYNC_();
  {
    const int r0 = side * 32;
    #pragma unroll
    for (int lay = 0; lay < 3; ++lay) {
      const int r = r0 + (tid >> 4), c4 = tid & 15;   // 512 threads = 32 rows x 16
      const int i4 = r * 16 + c4;
      float4 a = (lay < 2) ? SV4[lay * 1024 + i4] : S4[i4];
      const uint32_t poff = (lay < 2) ? (off_SAV + (uint32_t)(lay * 1024 + i4) * 16u)
                                      : (off_S + (uint32_t)i4 * 16u);
      add4(a, ld_ds4(pbase + poff));
      *reinterpret_cast<float4*>(out + (size_t)(base + r) * 256 + (size_t)(lay + 1) * 64 + c4 * 4) = a;
    }
  }
  CLUSTER_SYNC_();   // peer may still be reading our smem
}

} // namespace

extern "C" void kernel_launch(void* const* d_in, const int* in_sizes, int n_in,
                              void* d_out, int out_size) {
  const float* adj       = (const float*)d_in[0];
  const float* feat_node = (const float*)d_in[1];
  const int*   idx       = (const int*)  d_in[2];
  const int*   head_ids  = (const int*)  d_in[3];
  const int*   tail_ids  = (const int*)  d_in[4];
  // d_in[5] = graph_indices (implicit in block layout)
  const float* transform = (const float*)d_in[6];
  const float* embed     = (const float*)d_in[7];
  const float* w1        = (const float*)d_in[8];
  const float* b1        = (const float*)d_in[9];
  const float* w2        = (const float*)d_in[10];
  const float* b2        = (const float*)d_in[11];
  const float* gamma1    = (const float*)d_in[12];
  const float* beta1     = (const float*)d_in[13];
  const float* gamma2    = (const float*)d_in[14];
  const float* beta2     = (const float*)d_in[15];
  float* out = (float*)d_out;

  const int smem = (int)sizeof(Smem);
  cudaFuncSetAttribute(lagat_kernel, cudaFuncAttributeMaxDynamicSharedMemorySize, smem);
  lagat_kernel<<<128, NT, smem>>>(adj, feat_node, idx, head_ids, tail_ids,
                                  transform, embed, w1, b1, w2, b2,
                                  gamma1, beta1, gamma2, beta2, out);
}